// round 14
// baseline (speedup 1.0000x reference)
#include <cuda_runtime.h>
#include <cuda_bf16.h>
#include <stdint.h>
#include <math.h>

#define NMAX 50000
#define EMAX 800000

// ---------------- scratch (static __device__ — no allocation) ----------------
__device__ __nv_bfloat16 g_zb[(size_t)NMAX * 128];   // projections bf16 (GAT gather)
__device__ float g_el[(size_t)NMAX * 8];
__device__ float g_er[(size_t)NMAX * 8];
__device__ float g_h[(size_t)NMAX * 128];            // elu(gat)+x
__device__ __nv_bfloat16 g_xhi[(size_t)NMAX * 128];
__device__ __nv_bfloat16 g_xlo[(size_t)NMAX * 128];
__device__ __nv_bfloat16 g_lnvhi[(size_t)NMAX * 128];
__device__ __nv_bfloat16 g_lnvlo[(size_t)NMAX * 128];
__device__ __nv_bfloat16 g_inthi[(size_t)NMAX * 512];
__device__ __nv_bfloat16 g_intlo[(size_t)NMAX * 512];
__device__ __nv_bfloat16 g_fcwthi[128 * 128];        // B[n][k] = fc_w[h][k][o]
__device__ __nv_bfloat16 g_fcwtlo[128 * 128];
__device__ __nv_bfloat16 g_w1thi[512 * 128];         // B[n][k] = w1[k][n]
__device__ __nv_bfloat16 g_w1tlo[512 * 128];
__device__ __nv_bfloat16 g_w2thi[128 * 512];         // B[n][k] = w2[k][n]
__device__ __nv_bfloat16 g_w2tlo[128 * 512];
__device__ int g_cnt[NMAX];
__device__ int g_off[NMAX + 1];
__device__ int g_cur[NMAX];
__device__ int g_csrc[EMAX];

// ---------------- helpers ----------------
__device__ __forceinline__ uint32_t smem_to_u32(const void* p) {
    uint32_t a;
    asm("{ .reg .u64 t; cvta.to.shared.u64 t, %1; cvt.u32.u64 %0, t; }" : "=r"(a) : "l"(p));
    return a;
}
__device__ __forceinline__ void ldsm_x4(uint32_t& r0, uint32_t& r1, uint32_t& r2, uint32_t& r3,
                                        uint32_t addr) {
    asm volatile("ldmatrix.sync.aligned.m8n8.x4.shared.b16 {%0,%1,%2,%3}, [%4];"
                 : "=r"(r0), "=r"(r1), "=r"(r2), "=r"(r3) : "r"(addr));
}
__device__ __forceinline__ void mma16816(float* c, const uint32_t* a, const uint32_t* b) {
    asm volatile(
        "mma.sync.aligned.m16n8k16.row.col.f32.bf16.bf16.f32 "
        "{%0,%1,%2,%3}, {%4,%5,%6,%7}, {%8,%9}, {%0,%1,%2,%3};"
        : "+f"(c[0]), "+f"(c[1]), "+f"(c[2]), "+f"(c[3])
        : "r"(a[0]), "r"(a[1]), "r"(a[2]), "r"(a[3]), "r"(b[0]), "r"(b[1]));
}
__device__ __forceinline__ void cpa16(uint32_t d, const void* s) {
    asm volatile("cp.async.cg.shared.global [%0], [%1], 16;" :: "r"(d), "l"(s));
}
__device__ __forceinline__ float gelu_exact(float v) {
    return 0.5f * v * (1.0f + erff(v * 0.70710678118654752440f));
}
__device__ __forceinline__ void bsplit(float v, __nv_bfloat16& h, __nv_bfloat16& l) {
    h = __float2bfloat16(v);
    l = __float2bfloat16(v - __bfloat162float(h));
}
__device__ __forceinline__ unsigned pack_bf2(__nv_bfloat16 a, __nv_bfloat16 b) {
    unsigned short ua = *(unsigned short*)&a, ub = *(unsigned short*)&b;
    return (unsigned)ua | ((unsigned)ub << 16);
}
__device__ __forceinline__ unsigned pack_bf2f(float a, float b) {
    return pack_bf2(__float2bfloat16(a), __float2bfloat16(b));
}

// =====================================================================
// HMMA GEMM, cp.async double-buffered, CTA tile 256x64, 2 CTAs/SM.
// 256 threads = 8 warps (4m x 2n), warp tile 64x32, acc 64 f32/thread.
// Per 32-K chunk: 20KB loads for 1.57M MAC (0.0127 B/MAC -> compute-bound).
// EPI: 0 = proj: z -> bf16 out + fused el/er (bias=a_l, res=a_r)
//      1 = ffn1: gelu(acc+bias) -> bf16 hi/lo
//      2 = ffn2: acc+bias+res -> fp32
// =====================================================================
#define TILE_A 20480        // A array (256 rows x 80B)
#define TILE_Bb 5120        // B array (64 rows x 80B)
#define STAGE_B (2 * TILE_A + 2 * TILE_Bb)   // 51200

template<int KTOT, int EPI>
__global__ __launch_bounds__(256, 2) void mgemm_kernel(
    const __nv_bfloat16* __restrict__ Ahi, const __nv_bfloat16* __restrict__ Alo,
    const __nv_bfloat16* __restrict__ Bhi, const __nv_bfloat16* __restrict__ Blo,
    const float* __restrict__ bias, const float* __restrict__ res,
    float* __restrict__ outf, __nv_bfloat16* __restrict__ outhi,
    __nv_bfloat16* __restrict__ outlo, int M)
{
    extern __shared__ char smem[];
    const uint32_t sb = smem_to_u32(smem);

    const int tid = threadIdx.x;
    const int wid = tid >> 5, lane = tid & 31;
    const int wm = wid & 3, wn = wid >> 2;          // warp: rows wm*64, cols wn*32
    const int row0 = blockIdx.x * 256;
    const int col0 = blockIdx.y * 64;

    float acc[4][4][4];
#pragma unroll
    for (int i = 0; i < 4; i++)
#pragma unroll
        for (int j = 0; j < 4; j++)
#pragma unroll
            for (int p = 0; p < 4; p++) acc[i][j][p] = 0.f;

    const uint4* Ahi4 = (const uint4*)Ahi;
    const uint4* Alo4 = (const uint4*)Alo;
    const uint4* Bhi4 = (const uint4*)Bhi;
    const uint4* Blo4 = (const uint4*)Blo;
    constexpr int KU4 = KTOT / 8;
    constexpr int NK = KTOT / 32;

    // fill coords: A 4 rows/thread (hi+lo), B 1 row-chunk/thread (hi+lo)
    const int fr0 = tid >> 2, fc0 = tid & 3;
    int gar[4];
    uint32_t sbyA[4];
#pragma unroll
    for (int i = 0; i < 4; i++) {
        int fr = fr0 + i * 64;
        sbyA[i] = (uint32_t)(fr * 80 + fc0 * 16);
        int ga = row0 + fr; if (ga > M - 1) ga = M - 1;
        gar[i] = ga;
    }
    const int gb0 = col0 + fr0;                       // 64 B rows: t>>2 covers 0..63
    const uint32_t sbyB = (uint32_t)(fr0 * 80 + fc0 * 16);

    const int lg = lane >> 3, lr = lane & 7;
    const int a_row_off = lr + ((lg & 1) ? 8 : 0);
    const int a_k_off   = (lg >= 2) ? 8 : 0;
    const int b_row_off = lr + ((lg >= 2) ? 8 : 0);
    const int b_k_off   = (lg & 1) ? 8 : 0;

    auto load_stage = [&](int kc, int s) {
        const uint32_t st = sb + (uint32_t)s * STAGE_B;
        const int koff = kc * 4 + fc0;
#pragma unroll
        for (int i = 0; i < 4; i++) {
            cpa16(st + sbyA[i],          &Ahi4[(size_t)gar[i] * KU4 + koff]);
            cpa16(st + TILE_A + sbyA[i], &Alo4[(size_t)gar[i] * KU4 + koff]);
        }
        cpa16(st + 2 * TILE_A + sbyB,           &Bhi4[(size_t)gb0 * KU4 + koff]);
        cpa16(st + 2 * TILE_A + TILE_Bb + sbyB, &Blo4[(size_t)gb0 * KU4 + koff]);
        asm volatile("cp.async.commit_group;" ::: "memory");
    };

    load_stage(0, 0);

#pragma unroll 1
    for (int kc = 0; kc < NK; kc++) {
        asm volatile("cp.async.wait_group 0;" ::: "memory");
        __syncthreads();
        if (kc + 1 < NK) load_stage(kc + 1, (kc + 1) & 1);

        const uint32_t st = sb + (uint32_t)(kc & 1) * STAGE_B;
        const uint32_t sAh_b = st, sAl_b = st + TILE_A;
        const uint32_t sBh_b = st + 2 * TILE_A, sBl_b = st + 2 * TILE_A + TILE_Bb;

#pragma unroll
        for (int k16 = 0; k16 < 2; k16++) {
            const int kb = k16 * 16;
            uint32_t bh[8], bl[8];
#pragma unroll
            for (int np = 0; np < 2; np++) {
                uint32_t ab = (uint32_t)((wn * 32 + np * 16 + b_row_off) * 80 +
                                         (kb + b_k_off) * 2);
                ldsm_x4(bh[np * 4 + 0], bh[np * 4 + 1], bh[np * 4 + 2], bh[np * 4 + 3],
                        sBh_b + ab);
                ldsm_x4(bl[np * 4 + 0], bl[np * 4 + 1], bl[np * 4 + 2], bl[np * 4 + 3],
                        sBl_b + ab);
            }
#pragma unroll
            for (int mt = 0; mt < 4; mt++) {
                uint32_t aa = (uint32_t)((wm * 64 + mt * 16 + a_row_off) * 80 +
                                         (kb + a_k_off) * 2);
                uint32_t ah[4], al[4];
                ldsm_x4(ah[0], ah[1], ah[2], ah[3], sAh_b + aa);
                ldsm_x4(al[0], al[1], al[2], al[3], sAl_b + aa);
#pragma unroll
                for (int nt = 0; nt < 4; nt++) {
                    mma16816(acc[mt][nt], ah, &bh[nt * 2]);   // hi*hi
                    mma16816(acc[mt][nt], ah, &bl[nt * 2]);   // hi*lo
                    mma16816(acc[mt][nt], al, &bh[nt * 2]);   // lo*hi
                }
            }
        }
    }

    // ---- epilogue ----
    const int gid = lane >> 2, tg = lane & 3;
    constexpr int ONST = (EPI == 1) ? 512 : 128;

    if (EPI == 0) {
        const float* alp = bias;
        const float* arp = res;
        const int cbase = col0 + wn * 32;
        float alv[2][4], arv[2][4];
#pragma unroll
        for (int hh = 0; hh < 2; hh++) {
            int hd = (cbase >> 4) + hh;
#pragma unroll
            for (int q = 0; q < 4; q++) {
                int o = (q >> 1) * 8 + tg * 2 + (q & 1);
                alv[hh][q] = alp[hd * 16 + o];
                arv[hh][q] = arp[hd * 16 + o];
            }
        }
#pragma unroll
        for (int mt = 0; mt < 4; mt++) {
#pragma unroll
            for (int half = 0; half < 2; half++) {
                int grow = row0 + wm * 64 + mt * 16 + gid + half * 8;
                bool rok = (grow < M);
#pragma unroll
                for (int nt = 0; nt < 4; nt++) {
                    int col = cbase + nt * 8 + tg * 2;
                    if (rok)
                        *(unsigned*)&outhi[(size_t)grow * 128 + col] =
                            pack_bf2f(acc[mt][nt][half * 2 + 0], acc[mt][nt][half * 2 + 1]);
                }
#pragma unroll
                for (int hh = 0; hh < 2; hh++) {
                    float pl = acc[mt][hh * 2 + 0][half * 2 + 0] * alv[hh][0]
                             + acc[mt][hh * 2 + 0][half * 2 + 1] * alv[hh][1]
                             + acc[mt][hh * 2 + 1][half * 2 + 0] * alv[hh][2]
                             + acc[mt][hh * 2 + 1][half * 2 + 1] * alv[hh][3];
                    float pr = acc[mt][hh * 2 + 0][half * 2 + 0] * arv[hh][0]
                             + acc[mt][hh * 2 + 0][half * 2 + 1] * arv[hh][1]
                             + acc[mt][hh * 2 + 1][half * 2 + 0] * arv[hh][2]
                             + acc[mt][hh * 2 + 1][half * 2 + 1] * arv[hh][3];
                    pl += __shfl_xor_sync(0xffffffffu, pl, 1);
                    pl += __shfl_xor_sync(0xffffffffu, pl, 2);
                    pr += __shfl_xor_sync(0xffffffffu, pr, 1);
                    pr += __shfl_xor_sync(0xffffffffu, pr, 2);
                    if (tg == 0 && rok) {
                        int hd = (cbase >> 4) + hh;
                        g_el[grow * 8 + hd] = pl;
                        g_er[grow * 8 + hd] = pr;
                    }
                }
            }
        }
    } else {
#pragma unroll
        for (int mt = 0; mt < 4; mt++) {
#pragma unroll
            for (int half = 0; half < 2; half++) {
                int grow = row0 + wm * 64 + mt * 16 + gid + half * 8;
                if (grow >= M) continue;
#pragma unroll
                for (int nt = 0; nt < 4; nt++) {
                    int col = col0 + wn * 32 + nt * 8 + tg * 2;
                    float vx = acc[mt][nt][half * 2 + 0];
                    float vy = acc[mt][nt][half * 2 + 1];
                    if (EPI == 1) {
                        vx = gelu_exact(vx + bias[col]);
                        vy = gelu_exact(vy + bias[col + 1]);
                        __nv_bfloat16 bh0, bh1, bl0, bl1;
                        bsplit(vx, bh0, bl0);
                        bsplit(vy, bh1, bl1);
                        *(unsigned*)&outhi[(size_t)grow * ONST + col] = pack_bf2(bh0, bh1);
                        *(unsigned*)&outlo[(size_t)grow * ONST + col] = pack_bf2(bl0, bl1);
                    } else {
                        const float2 rv = *(const float2*)&res[(size_t)grow * 128 + col];
                        vx += bias[col] + rv.x;
                        vy += bias[col + 1] + rv.y;
                        *(float2*)&outf[(size_t)grow * 128 + col] = make_float2(vx, vy);
                    }
                }
            }
        }
    }
}

// =====================================================================
// prep: conversions only
// =====================================================================
__global__ void prep_kernel(const float* __restrict__ x,
                            const float* __restrict__ fcw,
                            const float* __restrict__ w1,
                            const float* __restrict__ w2, int n)
{
    int id = blockIdx.x * blockDim.x + threadIdx.x;
    int nx = n * 32;
    if (id < nx) {
        float4 v = ((const float4*)x)[id];
        __nv_bfloat16 bh0, bh1, bh2, bh3, bl0, bl1, bl2, bl3;
        bsplit(v.x, bh0, bl0); bsplit(v.y, bh1, bl1);
        bsplit(v.z, bh2, bl2); bsplit(v.w, bh3, bl3);
        ((uint2*)g_xhi)[id] = make_uint2(pack_bf2(bh0, bh1), pack_bf2(bh2, bh3));
        ((uint2*)g_xlo)[id] = make_uint2(pack_bf2(bl0, bl1), pack_bf2(bl2, bl3));
        return;
    }
    id -= nx;
    if (id < 128 * 128) {
        int nn = id >> 7, k = id & 127;
        int h = nn >> 4, o = nn & 15;
        float v = fcw[h * 2048 + k * 16 + o];
        __nv_bfloat16 bh, bl;
        bsplit(v, bh, bl);
        g_fcwthi[id] = bh; g_fcwtlo[id] = bl;
        return;
    }
    id -= 128 * 128;
    if (id < 512 * 128) {
        int nn = id >> 7, k = id & 127;       // B[n][k] = w1[k][n]
        float v = w1[k * 512 + nn];
        __nv_bfloat16 bh, bl;
        bsplit(v, bh, bl);
        g_w1thi[id] = bh; g_w1tlo[id] = bl;
        return;
    }
    id -= 512 * 128;
    if (id < 128 * 512) {
        int nn = id >> 9, k = id & 511;       // B[n][k] = w2[k][n]
        float v = w2[k * 128 + nn];
        __nv_bfloat16 bh, bl;
        bsplit(v, bh, bl);
        g_w2thi[id] = bh; g_w2tlo[id] = bl;
    }
}

// =====================================================================
// CSR build (side-stream chain: zero -> hist -> scan -> scatter)
// =====================================================================
__global__ void zero_cnt_kernel(int n) {
    int i = blockIdx.x * blockDim.x + threadIdx.x;
    if (i < n) g_cnt[i] = 0;
}
__global__ void hist_kernel(const int* __restrict__ dst, int E) {
    int i = blockIdx.x * blockDim.x + threadIdx.x;
    if (i < E) atomicAdd(&g_cnt[dst[i]], 1);
}
__global__ __launch_bounds__(1024) void scan_kernel(int n) {
    int t = threadIdx.x;
    int chunk = (n + 1023) >> 10;
    int b = t * chunk;
    int e = b + chunk; if (e > n) e = n;
    int s = 0;
    for (int i = b; i < e; i++) s += g_cnt[i];
    int own = s;
    int lane = t & 31, w = t >> 5;
#pragma unroll
    for (int d = 1; d < 32; d <<= 1) {
        int v = __shfl_up_sync(0xffffffffu, s, d);
        if (lane >= d) s += v;
    }
    __shared__ int ws[32];
    if (lane == 31) ws[w] = s;
    __syncthreads();
    if (w == 0) {
        int v = ws[lane];
#pragma unroll
        for (int d = 1; d < 32; d <<= 1) {
            int u = __shfl_up_sync(0xffffffffu, v, d);
            if (lane >= d) v += u;
        }
        ws[lane] = v;
    }
    __syncthreads();
    int run = s - own + (w ? ws[w - 1] : 0);
    for (int i = b; i < e; i++) {
        g_off[i] = run;
        g_cur[i] = run;
        run += g_cnt[i];
    }
    if (t == 1023) g_off[n] = ws[31];
}
__global__ void scatter_kernel(const int* __restrict__ src, const int* __restrict__ dst, int E) {
    int i = blockIdx.x * blockDim.x + threadIdx.x;
    if (i < E) {
        int d = dst[i];
        int p = atomicAdd(&g_cur[d], 1);
        g_csrc[p] = src[i];
    }
}

// =====================================================================
// GAT: single-pass softmax + aggregation (bf16 z gather) + elu +
// residual + fused LN. 4-way unrolled edge loop.
// =====================================================================
__device__ __forceinline__ float4 unpack_zb(uint2 u) {
    return make_float4(__uint_as_float((u.x & 0xffffu) << 16),
                       __uint_as_float(u.x & 0xffff0000u),
                       __uint_as_float((u.y & 0xffffu) << 16),
                       __uint_as_float(u.y & 0xffff0000u));
}

__global__ __launch_bounds__(256) void gat_ln_kernel(
    const float* __restrict__ x,
    const float* __restrict__ gg, const float* __restrict__ bb, int n)
{
    int warp = (blockIdx.x * blockDim.x + threadIdx.x) >> 5;
    int lane = threadIdx.x & 31;
    if (warp >= n) return;
    int d = warp;
    int beg = g_off[d], end = g_off[d + 1];

    int h2 = lane >> 2;
    float er_b = g_er[d * 8 + h2];

    float4 acc = make_float4(0.f, 0.f, 0.f, 0.f);
    float denom = 0.f;
    const uint2* zb = (const uint2*)g_zb;

    int i = beg;
    for (; i + 4 <= end; i += 4) {
        int s0 = g_csrc[i], s1 = g_csrc[i + 1], s2 = g_csrc[i + 2], s3 = g_csrc[i + 3];
        float e0 = g_el[s0 * 8 + h2] + er_b;
        float e1 = g_el[s1 * 8 + h2] + er_b;
        float e2 = g_el[s2 * 8 + h2] + er_b;
        float e3 = g_el[s3 * 8 + h2] + er_b;
        e0 = (e0 > 0.f) ? e0 : 0.01f * e0;
        e1 = (e1 > 0.f) ? e1 : 0.01f * e1;
        e2 = (e2 > 0.f) ? e2 : 0.01f * e2;
        e3 = (e3 > 0.f) ? e3 : 0.01f * e3;
        float ex0 = __expf(e0), ex1 = __expf(e1), ex2 = __expf(e2), ex3 = __expf(e3);
        float4 zv0 = unpack_zb(zb[(size_t)s0 * 32 + lane]);
        float4 zv1 = unpack_zb(zb[(size_t)s1 * 32 + lane]);
        float4 zv2 = unpack_zb(zb[(size_t)s2 * 32 + lane]);
        float4 zv3 = unpack_zb(zb[(size_t)s3 * 32 + lane]);
        denom += (ex0 + ex1) + (ex2 + ex3);
        acc.x += ex0 * zv0.x + ex1 * zv1.x + ex2 * zv2.x + ex3 * zv3.x;
        acc.y += ex0 * zv0.y + ex1 * zv1.y + ex2 * zv2.y + ex3 * zv3.y;
        acc.z += ex0 * zv0.z + ex1 * zv1.z + ex2 * zv2.z + ex3 * zv3.z;
        acc.w += ex0 * zv0.w + ex1 * zv1.w + ex2 * zv2.w + ex3 * zv3.w;
    }
    for (; i < end; i++) {
        int s0 = g_csrc[i];
        float e0 = g_el[s0 * 8 + h2] + er_b;
        e0 = (e0 > 0.f) ? e0 : 0.01f * e0;
        float ex0 = __expf(e0);
        float4 zv0 = unpack_zb(zb[(size_t)s0 * 32 + lane]);
        denom += ex0;
        acc.x += ex0 * zv0.x;
        acc.y += ex0 * zv0.y;
        acc.z += ex0 * zv0.z;
        acc.w += ex0 * zv0.w;
    }

    float rd = (denom > 0.f) ? (1.0f / denom) : 0.f;
    acc.x *= rd; acc.y *= rd; acc.z *= rd; acc.w *= rd;

    float4 xr = ((const float4*)x)[(size_t)d * 32 + lane];
    acc.x = ((acc.x > 0.f) ? acc.x : (__expf(acc.x) - 1.f)) + xr.x;
    acc.y = ((acc.y > 0.f) ? acc.y : (__expf(acc.y) - 1.f)) + xr.y;
    acc.z = ((acc.z > 0.f) ? acc.z : (__expf(acc.z) - 1.f)) + xr.z;
    acc.w = ((acc.w > 0.f) ? acc.w : (__expf(acc.w) - 1.f)) + xr.w;
    ((float4*)g_h)[(size_t)d * 32 + lane] = acc;

    float s = acc.x + acc.y + acc.z + acc.w;
#pragma unroll
    for (int o = 16; o; o >>= 1) s += __shfl_xor_sync(0xffffffffu, s, o);
    float mu = s * (1.f / 128.f);
    float dx = acc.x - mu, dy = acc.y - mu, dz = acc.z - mu, dw = acc.w - mu;
    float q = dx * dx + dy * dy + dz * dz + dw * dw;
#pragma unroll
    for (int o = 16; o; o >>= 1) q += __shfl_xor_sync(0xffffffffu, q, o);
    float rs = rsqrtf(q * (1.f / 128.f) + 1e-6f);
    float4 g4 = ((const float4*)gg)[lane];
    float4 b4 = ((const float4*)bb)[lane];
    float4 o4 = make_float4(dx * rs * g4.x + b4.x, dy * rs * g4.y + b4.y,
                            dz * rs * g4.z + b4.z, dw * rs * g4.w + b4.w);
    __nv_bfloat16 bh0, bh1, bh2, bh3, bl0, bl1, bl2, bl3;
    bsplit(o4.x, bh0, bl0); bsplit(o4.y, bh1, bl1);
    bsplit(o4.z, bh2, bl2); bsplit(o4.w, bh3, bl3);
    ((uint2*)g_lnvhi)[(size_t)d * 32 + lane] = make_uint2(pack_bf2(bh0, bh1), pack_bf2(bh2, bh3));
    ((uint2*)g_lnvlo)[(size_t)d * 32 + lane] = make_uint2(pack_bf2(bl0, bl1), pack_bf2(bl2, bl3));
}

// =====================================================================
extern "C" void kernel_launch(void* const* d_in, const int* in_sizes, int n_in,
                              void* d_out, int out_size)
{
    const float* x    = (const float*)d_in[0];
    const float* fcw  = (const float*)d_in[1];
    const float* a_l  = (const float*)d_in[2];
    const float* a_r  = (const float*)d_in[3];
    const float* ln_g = (const float*)d_in[4];
    const float* ln_b = (const float*)d_in[5];
    const float* w1   = (const float*)d_in[6];
    const float* b1   = (const float*)d_in[7];
    const float* w2   = (const float*)d_in[8];
    const float* b2   = (const float*)d_in[9];
    const int*   src  = (const int*)d_in[10];
    const int*   dst  = (const int*)d_in[11];

    int n = in_sizes[0] / 128;
    int E = in_sizes[10];

    float* g_h_p;
    __nv_bfloat16 *zb, *xhi, *xlo, *lnvhi, *lnvlo, *inthi, *intlo;
    __nv_bfloat16 *fcwhi, *fcwlo, *w1hi, *w1lo, *w2hi, *w2lo;
    cudaGetSymbolAddress((void**)&g_h_p, g_h);
    cudaGetSymbolAddress((void**)&zb, g_zb);
    cudaGetSymbolAddress((void**)&xhi, g_xhi);
    cudaGetSymbolAddress((void**)&xlo, g_xlo);
    cudaGetSymbolAddress((void**)&lnvhi, g_lnvhi);
    cudaGetSymbolAddress((void**)&lnvlo, g_lnvlo);
    cudaGetSymbolAddress((void**)&inthi, g_inthi);
    cudaGetSymbolAddress((void**)&intlo, g_intlo);
    cudaGetSymbolAddress((void**)&fcwhi, g_fcwthi);
    cudaGetSymbolAddress((void**)&fcwlo, g_fcwtlo);
    cudaGetSymbolAddress((void**)&w1hi, g_w1thi);
    cudaGetSymbolAddress((void**)&w1lo, g_w1tlo);
    cudaGetSymbolAddress((void**)&w2hi, g_w2thi);
    cudaGetSymbolAddress((void**)&w2lo, g_w2tlo);

    // lazy one-time host-side infra (created on first, uncaptured call)
    static cudaStream_t s_side = nullptr;
    static cudaEvent_t ev_fork = nullptr, ev_join = nullptr;
    if (s_side == nullptr) {
        cudaStreamCreateWithFlags(&s_side, cudaStreamNonBlocking);
        cudaEventCreateWithFlags(&ev_fork, cudaEventDisableTiming);
        cudaEventCreateWithFlags(&ev_join, cudaEventDisableTiming);
    }

    const int SMEM_SZ = 2 * STAGE_B;   // 102400
    cudaFuncSetAttribute(mgemm_kernel<128, 0>, cudaFuncAttributeMaxDynamicSharedMemorySize, SMEM_SZ);
    cudaFuncSetAttribute(mgemm_kernel<128, 1>, cudaFuncAttributeMaxDynamicSharedMemorySize, SMEM_SZ);
    cudaFuncSetAttribute(mgemm_kernel<512, 2>, cudaFuncAttributeMaxDynamicSharedMemorySize, SMEM_SZ);

    int mblk = (n + 255) / 256;

    // ---- fork: CSR chain on side stream ----
    cudaEventRecord(ev_fork, 0);
    cudaStreamWaitEvent(s_side, ev_fork, 0);

    zero_cnt_kernel<<<(n + 255) / 256, 256, 0, s_side>>>(n);
    hist_kernel<<<(E + 255) / 256, 256, 0, s_side>>>(dst, E);
    scan_kernel<<<1, 1024, 0, s_side>>>(n);
    scatter_kernel<<<(E + 255) / 256, 256, 0, s_side>>>(src, dst, E);
    cudaEventRecord(ev_join, s_side);

    // ---- main stream: conversions -> proj(+el/er fused) ----
    int prep_items = n * 32 + 128 * 128 + 512 * 128 + 128 * 512;
    prep_kernel<<<(prep_items + 255) / 256, 256>>>(x, fcw, w1, w2, n);

    mgemm_kernel<128, 0><<<dim3(mblk, 2), 256, SMEM_SZ>>>(
        xhi, xlo, fcwhi, fcwlo, a_l, a_r, nullptr, zb, nullptr, n);

    // ---- join: gat_ln needs CSR + proj ----
    cudaStreamWaitEvent(0, ev_join, 0);
    gat_ln_kernel<<<(n + 7) / 8, 256>>>(x, ln_g, ln_b, n);

    // FFN (HMMA)
    mgemm_kernel<128, 1><<<dim3(mblk, 8), 256, SMEM_SZ>>>(
        lnvhi, lnvlo, w1hi, w1lo, b1, nullptr, nullptr, inthi, intlo, n);
    mgemm_kernel<512, 2><<<dim3(mblk, 2), 256, SMEM_SZ>>>(
        inthi, intlo, w2hi, w2lo, b2, g_h_p, (float*)d_out, nullptr, nullptr, n);
}

// round 15
// speedup vs baseline: 1.0091x; 1.0091x over previous
#include <cuda_runtime.h>
#include <cuda_bf16.h>
#include <stdint.h>
#include <math.h>

#define NMAX 50000
#define EMAX 800000

// ---------------- scratch (static __device__ — no allocation) ----------------
__device__ __nv_bfloat16 g_zb[(size_t)NMAX * 128];   // projections bf16 (GAT gather)
__device__ float g_el[(size_t)NMAX * 8];
__device__ float g_er[(size_t)NMAX * 8];
__device__ float g_h[(size_t)NMAX * 128];            // elu(gat)+x
__device__ __nv_bfloat16 g_xb[(size_t)NMAX * 128];   // x bf16 (proj A)
__device__ __nv_bfloat16 g_lnvhi[(size_t)NMAX * 128];
__device__ __nv_bfloat16 g_lnvlo[(size_t)NMAX * 128];
__device__ __nv_bfloat16 g_inthi[(size_t)NMAX * 512];
__device__ __nv_bfloat16 g_intlo[(size_t)NMAX * 512];
__device__ __nv_bfloat16 g_fcwt[128 * 128];          // B[n][k] = fc_w[h][k][o], bf16
__device__ __nv_bfloat16 g_w1thi[512 * 128];         // B[n][k] = w1[k][n]
__device__ __nv_bfloat16 g_w1tlo[512 * 128];
__device__ __nv_bfloat16 g_w2thi[128 * 512];         // B[n][k] = w2[k][n]
__device__ __nv_bfloat16 g_w2tlo[128 * 512];
__device__ int g_cnt[NMAX];
__device__ int g_off[NMAX + 1];
__device__ int g_cur[NMAX];
__device__ int g_csrc[EMAX];

// ---------------- helpers ----------------
__device__ __forceinline__ uint32_t smem_to_u32(const void* p) {
    uint32_t a;
    asm("{ .reg .u64 t; cvta.to.shared.u64 t, %1; cvt.u32.u64 %0, t; }" : "=r"(a) : "l"(p));
    return a;
}
__device__ __forceinline__ void ldsm_x4(uint32_t& r0, uint32_t& r1, uint32_t& r2, uint32_t& r3,
                                        uint32_t addr) {
    asm volatile("ldmatrix.sync.aligned.m8n8.x4.shared.b16 {%0,%1,%2,%3}, [%4];"
                 : "=r"(r0), "=r"(r1), "=r"(r2), "=r"(r3) : "r"(addr));
}
__device__ __forceinline__ void mma16816(float* c, const uint32_t* a, const uint32_t* b) {
    asm volatile(
        "mma.sync.aligned.m16n8k16.row.col.f32.bf16.bf16.f32 "
        "{%0,%1,%2,%3}, {%4,%5,%6,%7}, {%8,%9}, {%0,%1,%2,%3};"
        : "+f"(c[0]), "+f"(c[1]), "+f"(c[2]), "+f"(c[3])
        : "r"(a[0]), "r"(a[1]), "r"(a[2]), "r"(a[3]), "r"(b[0]), "r"(b[1]));
}
__device__ __forceinline__ void cpa16(uint32_t d, const void* s) {
    asm volatile("cp.async.cg.shared.global [%0], [%1], 16;" :: "r"(d), "l"(s));
}
__device__ __forceinline__ float gelu_exact(float v) {
    return 0.5f * v * (1.0f + erff(v * 0.70710678118654752440f));
}
__device__ __forceinline__ void bsplit(float v, __nv_bfloat16& h, __nv_bfloat16& l) {
    h = __float2bfloat16(v);
    l = __float2bfloat16(v - __bfloat162float(h));
}
__device__ __forceinline__ unsigned pack_bf2(__nv_bfloat16 a, __nv_bfloat16 b) {
    unsigned short ua = *(unsigned short*)&a, ub = *(unsigned short*)&b;
    return (unsigned)ua | ((unsigned)ub << 16);
}
__device__ __forceinline__ unsigned pack_bf2f(float a, float b) {
    return pack_bf2(__float2bfloat16(a), __float2bfloat16(b));
}

// =====================================================================
// HMMA GEMM, cp.async double-buffered, CTA tile 128x64, 3 CTAs/SM,
// single-sync mainloop. NT = compensation terms (1 or 3).
// EPI: 0 = proj (NT=1): z -> bf16 + fused el/er (bias=a_l, res=a_r)
//      1 = ffn1 (NT=3): gelu(acc+bias) -> bf16 hi/lo
//      2 = ffn2 (NT=3): acc+bias+res -> fp32
// =====================================================================
#define TILE_A 10240        // A array (128 rows x 80B)
#define TILE_Bb 5120        // B array (64 rows x 80B)

template<int KTOT, int EPI, int NT>
__global__ __launch_bounds__(256, 3) void mgemm_kernel(
    const __nv_bfloat16* __restrict__ Ahi, const __nv_bfloat16* __restrict__ Alo,
    const __nv_bfloat16* __restrict__ Bhi, const __nv_bfloat16* __restrict__ Blo,
    const float* __restrict__ bias, const float* __restrict__ res,
    float* __restrict__ outf, __nv_bfloat16* __restrict__ outhi,
    __nv_bfloat16* __restrict__ outlo, int M)
{
    constexpr uint32_t AH = 0;
    constexpr uint32_t AL = TILE_A;                       // NT=3 only
    constexpr uint32_t BH = (NT == 1) ? TILE_A : 2 * TILE_A;
    constexpr uint32_t BL = BH + TILE_Bb;                 // NT=3 only
    constexpr uint32_t STG = (NT == 1) ? (TILE_A + TILE_Bb)
                                       : (2 * TILE_A + 2 * TILE_Bb);

    extern __shared__ char smem[];
    const uint32_t sb = smem_to_u32(smem);

    const int tid = threadIdx.x;
    const int wid = tid >> 5, lane = tid & 31;
    const int wm = wid & 3, wn = wid >> 2;
    const int row0 = blockIdx.x * 128;
    const int col0 = blockIdx.y * 64;

    float acc[2][4][4];
#pragma unroll
    for (int i = 0; i < 2; i++)
#pragma unroll
        for (int j = 0; j < 4; j++)
#pragma unroll
            for (int p = 0; p < 4; p++) acc[i][j][p] = 0.f;

    const uint4* Ahi4 = (const uint4*)Ahi;
    const uint4* Alo4 = (const uint4*)Alo;
    const uint4* Bhi4 = (const uint4*)Bhi;
    const uint4* Blo4 = (const uint4*)Blo;
    constexpr int KU4 = KTOT / 8;
    constexpr int NK = KTOT / 32;

    const int fr0 = tid >> 2, fc0 = tid & 3;
    const int fr1 = fr0 + 64;
    const uint32_t sby0 = (uint32_t)(fr0 * 80 + fc0 * 16);
    const uint32_t sby1 = (uint32_t)(fr1 * 80 + fc0 * 16);
    int ga0 = row0 + fr0; if (ga0 > M - 1) ga0 = M - 1;
    int ga1 = row0 + fr1; if (ga1 > M - 1) ga1 = M - 1;
    const int gb0 = col0 + fr0;

    const int lg = lane >> 3, lr = lane & 7;
    const int a_row_off = lr + ((lg & 1) ? 8 : 0);
    const int a_k_off   = (lg >= 2) ? 8 : 0;
    const int b_row_off = lr + ((lg >= 2) ? 8 : 0);
    const int b_k_off   = (lg & 1) ? 8 : 0;

    auto load_stage = [&](int kc, int s) {
        const uint32_t st = sb + (uint32_t)s * STG;
        const int koff = kc * 4 + fc0;
        cpa16(st + AH + sby0, &Ahi4[(size_t)ga0 * KU4 + koff]);
        cpa16(st + AH + sby1, &Ahi4[(size_t)ga1 * KU4 + koff]);
        cpa16(st + BH + sby0, &Bhi4[(size_t)gb0 * KU4 + koff]);
        if (NT == 3) {
            cpa16(st + AL + sby0, &Alo4[(size_t)ga0 * KU4 + koff]);
            cpa16(st + AL + sby1, &Alo4[(size_t)ga1 * KU4 + koff]);
            cpa16(st + BL + sby0, &Blo4[(size_t)gb0 * KU4 + koff]);
        }
        asm volatile("cp.async.commit_group;" ::: "memory");
    };

    load_stage(0, 0);

#pragma unroll 1
    for (int kc = 0; kc < NK; kc++) {
        asm volatile("cp.async.wait_group 0;" ::: "memory");
        __syncthreads();
        if (kc + 1 < NK) load_stage(kc + 1, (kc + 1) & 1);

        const uint32_t st = sb + (uint32_t)(kc & 1) * STG;

#pragma unroll
        for (int k16 = 0; k16 < 2; k16++) {
            const int kb = k16 * 16;
            uint32_t bh[8], bl[8];
#pragma unroll
            for (int np = 0; np < 2; np++) {
                uint32_t ab = (uint32_t)((wn * 32 + np * 16 + b_row_off) * 80 +
                                         (kb + b_k_off) * 2);
                ldsm_x4(bh[np * 4 + 0], bh[np * 4 + 1], bh[np * 4 + 2], bh[np * 4 + 3],
                        st + BH + ab);
                if (NT == 3)
                    ldsm_x4(bl[np * 4 + 0], bl[np * 4 + 1], bl[np * 4 + 2], bl[np * 4 + 3],
                            st + BL + ab);
            }
#pragma unroll
            for (int mt = 0; mt < 2; mt++) {
                uint32_t aa = (uint32_t)((wm * 32 + mt * 16 + a_row_off) * 80 +
                                         (kb + a_k_off) * 2);
                uint32_t ah[4], al[4];
                ldsm_x4(ah[0], ah[1], ah[2], ah[3], st + AH + aa);
                if (NT == 3)
                    ldsm_x4(al[0], al[1], al[2], al[3], st + AL + aa);
#pragma unroll
                for (int nt = 0; nt < 4; nt++) {
                    mma16816(acc[mt][nt], ah, &bh[nt * 2]);       // hi*hi
                    if (NT == 3) {
                        mma16816(acc[mt][nt], ah, &bl[nt * 2]);   // hi*lo
                        mma16816(acc[mt][nt], al, &bh[nt * 2]);   // lo*hi
                    }
                }
            }
        }
    }

    // ---- epilogue ----
    const int gid = lane >> 2, tg = lane & 3;
    constexpr int ONST = (EPI == 1) ? 512 : 128;

    if (EPI == 0) {
        const float* alp = bias;
        const float* arp = res;
        const int cbase = col0 + wn * 32;
        float alv[2][4], arv[2][4];
#pragma unroll
        for (int hh = 0; hh < 2; hh++) {
            int hd = (cbase >> 4) + hh;
#pragma unroll
            for (int q = 0; q < 4; q++) {
                int o = (q >> 1) * 8 + tg * 2 + (q & 1);
                alv[hh][q] = alp[hd * 16 + o];
                arv[hh][q] = arp[hd * 16 + o];
            }
        }
#pragma unroll
        for (int mt = 0; mt < 2; mt++) {
#pragma unroll
            for (int half = 0; half < 2; half++) {
                int grow = row0 + wm * 32 + mt * 16 + gid + half * 8;
                bool rok = (grow < M);
#pragma unroll
                for (int nt = 0; nt < 4; nt++) {
                    int col = cbase + nt * 8 + tg * 2;
                    if (rok)
                        *(unsigned*)&outhi[(size_t)grow * 128 + col] =
                            pack_bf2f(acc[mt][nt][half * 2 + 0], acc[mt][nt][half * 2 + 1]);
                }
#pragma unroll
                for (int hh = 0; hh < 2; hh++) {
                    float pl = acc[mt][hh * 2 + 0][half * 2 + 0] * alv[hh][0]
                             + acc[mt][hh * 2 + 0][half * 2 + 1] * alv[hh][1]
                             + acc[mt][hh * 2 + 1][half * 2 + 0] * alv[hh][2]
                             + acc[mt][hh * 2 + 1][half * 2 + 1] * alv[hh][3];
                    float pr = acc[mt][hh * 2 + 0][half * 2 + 0] * arv[hh][0]
                             + acc[mt][hh * 2 + 0][half * 2 + 1] * arv[hh][1]
                             + acc[mt][hh * 2 + 1][half * 2 + 0] * arv[hh][2]
                             + acc[mt][hh * 2 + 1][half * 2 + 1] * arv[hh][3];
                    pl += __shfl_xor_sync(0xffffffffu, pl, 1);
                    pl += __shfl_xor_sync(0xffffffffu, pl, 2);
                    pr += __shfl_xor_sync(0xffffffffu, pr, 1);
                    pr += __shfl_xor_sync(0xffffffffu, pr, 2);
                    if (tg == 0 && rok) {
                        int hd = (cbase >> 4) + hh;
                        g_el[grow * 8 + hd] = pl;
                        g_er[grow * 8 + hd] = pr;
                    }
                }
            }
        }
    } else {
#pragma unroll
        for (int mt = 0; mt < 2; mt++) {
#pragma unroll
            for (int half = 0; half < 2; half++) {
                int grow = row0 + wm * 32 + mt * 16 + gid + half * 8;
                if (grow >= M) continue;
#pragma unroll
                for (int nt = 0; nt < 4; nt++) {
                    int col = col0 + wn * 32 + nt * 8 + tg * 2;
                    float vx = acc[mt][nt][half * 2 + 0];
                    float vy = acc[mt][nt][half * 2 + 1];
                    if (EPI == 1) {
                        vx = gelu_exact(vx + bias[col]);
                        vy = gelu_exact(vy + bias[col + 1]);
                        __nv_bfloat16 bh0, bh1, bl0, bl1;
                        bsplit(vx, bh0, bl0);
                        bsplit(vy, bh1, bl1);
                        *(unsigned*)&outhi[(size_t)grow * ONST + col] = pack_bf2(bh0, bh1);
                        *(unsigned*)&outlo[(size_t)grow * ONST + col] = pack_bf2(bl0, bl1);
                    } else {
                        const float2 rv = *(const float2*)&res[(size_t)grow * 128 + col];
                        vx += bias[col] + rv.x;
                        vy += bias[col + 1] + rv.y;
                        *(float2*)&outf[(size_t)grow * 128 + col] = make_float2(vx, vy);
                    }
                }
            }
        }
    }
}

// =====================================================================
// prep: conversions (x, fcw plain bf16; w1/w2 split hi/lo)
// =====================================================================
__global__ void prep_kernel(const float* __restrict__ x,
                            const float* __restrict__ fcw,
                            const float* __restrict__ w1,
                            const float* __restrict__ w2, int n)
{
    int id = blockIdx.x * blockDim.x + threadIdx.x;
    int nx = n * 32;
    if (id < nx) {
        float4 v = ((const float4*)x)[id];
        ((uint2*)g_xb)[id] = make_uint2(pack_bf2f(v.x, v.y), pack_bf2f(v.z, v.w));
        return;
    }
    id -= nx;
    if (id < 128 * 128) {
        int nn = id >> 7, k = id & 127;
        int h = nn >> 4, o = nn & 15;
        g_fcwt[id] = __float2bfloat16(fcw[h * 2048 + k * 16 + o]);
        return;
    }
    id -= 128 * 128;
    if (id < 512 * 128) {
        int nn = id >> 7, k = id & 127;       // B[n][k] = w1[k][n]
        float v = w1[k * 512 + nn];
        __nv_bfloat16 bh, bl;
        bsplit(v, bh, bl);
        g_w1thi[id] = bh; g_w1tlo[id] = bl;
        return;
    }
    id -= 512 * 128;
    if (id < 128 * 512) {
        int nn = id >> 9, k = id & 511;       // B[n][k] = w2[k][n]
        float v = w2[k * 128 + nn];
        __nv_bfloat16 bh, bl;
        bsplit(v, bh, bl);
        g_w2thi[id] = bh; g_w2tlo[id] = bl;
    }
}

// =====================================================================
// CSR build (side-stream chain: zero -> hist -> scan -> scatter)
// =====================================================================
__global__ void zero_cnt_kernel(int n) {
    int i = blockIdx.x * blockDim.x + threadIdx.x;
    if (i < n) g_cnt[i] = 0;
}
__global__ void hist_kernel(const int* __restrict__ dst, int E) {
    int i = blockIdx.x * blockDim.x + threadIdx.x;
    if (i < E) atomicAdd(&g_cnt[dst[i]], 1);
}
__global__ __launch_bounds__(1024) void scan_kernel(int n) {
    int t = threadIdx.x;
    int chunk = (n + 1023) >> 10;
    int b = t * chunk;
    int e = b + chunk; if (e > n) e = n;
    int s = 0;
    for (int i = b; i < e; i++) s += g_cnt[i];
    int own = s;
    int lane = t & 31, w = t >> 5;
#pragma unroll
    for (int d = 1; d < 32; d <<= 1) {
        int v = __shfl_up_sync(0xffffffffu, s, d);
        if (lane >= d) s += v;
    }
    __shared__ int ws[32];
    if (lane == 31) ws[w] = s;
    __syncthreads();
    if (w == 0) {
        int v = ws[lane];
#pragma unroll
        for (int d = 1; d < 32; d <<= 1) {
            int u = __shfl_up_sync(0xffffffffu, v, d);
            if (lane >= d) v += u;
        }
        ws[lane] = v;
    }
    __syncthreads();
    int run = s - own + (w ? ws[w - 1] : 0);
    for (int i = b; i < e; i++) {
        g_off[i] = run;
        g_cur[i] = run;
        run += g_cnt[i];
    }
    if (t == 1023) g_off[n] = ws[31];
}
__global__ void scatter_kernel(const int* __restrict__ src, const int* __restrict__ dst, int E) {
    int i = blockIdx.x * blockDim.x + threadIdx.x;
    if (i < E) {
        int d = dst[i];
        int p = atomicAdd(&g_cur[d], 1);
        g_csrc[p] = src[i];
    }
}

// =====================================================================
// GAT: single-pass softmax + aggregation (bf16 z gather) + elu +
// residual + fused LN. 4-way unrolled edge loop.
// =====================================================================
__device__ __forceinline__ float4 unpack_zb(uint2 u) {
    return make_float4(__uint_as_float((u.x & 0xffffu) << 16),
                       __uint_as_float(u.x & 0xffff0000u),
                       __uint_as_float((u.y & 0xffffu) << 16),
                       __uint_as_float(u.y & 0xffff0000u));
}

__global__ __launch_bounds__(256) void gat_ln_kernel(
    const float* __restrict__ x,
    const float* __restrict__ gg, const float* __restrict__ bb, int n)
{
    int warp = (blockIdx.x * blockDim.x + threadIdx.x) >> 5;
    int lane = threadIdx.x & 31;
    if (warp >= n) return;
    int d = warp;
    int beg = g_off[d], end = g_off[d + 1];

    int h2 = lane >> 2;
    float er_b = g_er[d * 8 + h2];

    float4 acc = make_float4(0.f, 0.f, 0.f, 0.f);
    float denom = 0.f;
    const uint2* zb = (const uint2*)g_zb;

    int i = beg;
    for (; i + 4 <= end; i += 4) {
        int s0 = g_csrc[i], s1 = g_csrc[i + 1], s2 = g_csrc[i + 2], s3 = g_csrc[i + 3];
        float e0 = g_el[s0 * 8 + h2] + er_b;
        float e1 = g_el[s1 * 8 + h2] + er_b;
        float e2 = g_el[s2 * 8 + h2] + er_b;
        float e3 = g_el[s3 * 8 + h2] + er_b;
        e0 = (e0 > 0.f) ? e0 : 0.01f * e0;
        e1 = (e1 > 0.f) ? e1 : 0.01f * e1;
        e2 = (e2 > 0.f) ? e2 : 0.01f * e2;
        e3 = (e3 > 0.f) ? e3 : 0.01f * e3;
        float ex0 = __expf(e0), ex1 = __expf(e1), ex2 = __expf(e2), ex3 = __expf(e3);
        float4 zv0 = unpack_zb(zb[(size_t)s0 * 32 + lane]);
        float4 zv1 = unpack_zb(zb[(size_t)s1 * 32 + lane]);
        float4 zv2 = unpack_zb(zb[(size_t)s2 * 32 + lane]);
        float4 zv3 = unpack_zb(zb[(size_t)s3 * 32 + lane]);
        denom += (ex0 + ex1) + (ex2 + ex3);
        acc.x += ex0 * zv0.x + ex1 * zv1.x + ex2 * zv2.x + ex3 * zv3.x;
        acc.y += ex0 * zv0.y + ex1 * zv1.y + ex2 * zv2.y + ex3 * zv3.y;
        acc.z += ex0 * zv0.z + ex1 * zv1.z + ex2 * zv2.z + ex3 * zv3.z;
        acc.w += ex0 * zv0.w + ex1 * zv1.w + ex2 * zv2.w + ex3 * zv3.w;
    }
    for (; i < end; i++) {
        int s0 = g_csrc[i];
        float e0 = g_el[s0 * 8 + h2] + er_b;
        e0 = (e0 > 0.f) ? e0 : 0.01f * e0;
        float ex0 = __expf(e0);
        float4 zv0 = unpack_zb(zb[(size_t)s0 * 32 + lane]);
        denom += ex0;
        acc.x += ex0 * zv0.x;
        acc.y += ex0 * zv0.y;
        acc.z += ex0 * zv0.z;
        acc.w += ex0 * zv0.w;
    }

    float rd = (denom > 0.f) ? (1.0f / denom) : 0.f;
    acc.x *= rd; acc.y *= rd; acc.z *= rd; acc.w *= rd;

    float4 xr = ((const float4*)x)[(size_t)d * 32 + lane];
    acc.x = ((acc.x > 0.f) ? acc.x : (__expf(acc.x) - 1.f)) + xr.x;
    acc.y = ((acc.y > 0.f) ? acc.y : (__expf(acc.y) - 1.f)) + xr.y;
    acc.z = ((acc.z > 0.f) ? acc.z : (__expf(acc.z) - 1.f)) + xr.z;
    acc.w = ((acc.w > 0.f) ? acc.w : (__expf(acc.w) - 1.f)) + xr.w;
    ((float4*)g_h)[(size_t)d * 32 + lane] = acc;

    float s = acc.x + acc.y + acc.z + acc.w;
#pragma unroll
    for (int o = 16; o; o >>= 1) s += __shfl_xor_sync(0xffffffffu, s, o);
    float mu = s * (1.f / 128.f);
    float dx = acc.x - mu, dy = acc.y - mu, dz = acc.z - mu, dw = acc.w - mu;
    float q = dx * dx + dy * dy + dz * dz + dw * dw;
#pragma unroll
    for (int o = 16; o; o >>= 1) q += __shfl_xor_sync(0xffffffffu, q, o);
    float rs = rsqrtf(q * (1.f / 128.f) + 1e-6f);
    float4 g4 = ((const float4*)gg)[lane];
    float4 b4 = ((const float4*)bb)[lane];
    float4 o4 = make_float4(dx * rs * g4.x + b4.x, dy * rs * g4.y + b4.y,
                            dz * rs * g4.z + b4.z, dw * rs * g4.w + b4.w);
    __nv_bfloat16 bh0, bh1, bh2, bh3, bl0, bl1, bl2, bl3;
    bsplit(o4.x, bh0, bl0); bsplit(o4.y, bh1, bl1);
    bsplit(o4.z, bh2, bl2); bsplit(o4.w, bh3, bl3);
    ((uint2*)g_lnvhi)[(size_t)d * 32 + lane] = make_uint2(pack_bf2(bh0, bh1), pack_bf2(bh2, bh3));
    ((uint2*)g_lnvlo)[(size_t)d * 32 + lane] = make_uint2(pack_bf2(bl0, bl1), pack_bf2(bl2, bl3));
}

// =====================================================================
extern "C" void kernel_launch(void* const* d_in, const int* in_sizes, int n_in,
                              void* d_out, int out_size)
{
    const float* x    = (const float*)d_in[0];
    const float* fcw  = (const float*)d_in[1];
    const float* a_l  = (const float*)d_in[2];
    const float* a_r  = (const float*)d_in[3];
    const float* ln_g = (const float*)d_in[4];
    const float* ln_b = (const float*)d_in[5];
    const float* w1   = (const float*)d_in[6];
    const float* b1   = (const float*)d_in[7];
    const float* w2   = (const float*)d_in[8];
    const float* b2   = (const float*)d_in[9];
    const int*   src  = (const int*)d_in[10];
    const int*   dst  = (const int*)d_in[11];

    int n = in_sizes[0] / 128;
    int E = in_sizes[10];

    float* g_h_p;
    __nv_bfloat16 *zb, *xb, *lnvhi, *lnvlo, *inthi, *intlo;
    __nv_bfloat16 *fcwt, *w1hi, *w1lo, *w2hi, *w2lo;
    cudaGetSymbolAddress((void**)&g_h_p, g_h);
    cudaGetSymbolAddress((void**)&zb, g_zb);
    cudaGetSymbolAddress((void**)&xb, g_xb);
    cudaGetSymbolAddress((void**)&lnvhi, g_lnvhi);
    cudaGetSymbolAddress((void**)&lnvlo, g_lnvlo);
    cudaGetSymbolAddress((void**)&inthi, g_inthi);
    cudaGetSymbolAddress((void**)&intlo, g_intlo);
    cudaGetSymbolAddress((void**)&fcwt, g_fcwt);
    cudaGetSymbolAddress((void**)&w1hi, g_w1thi);
    cudaGetSymbolAddress((void**)&w1lo, g_w1tlo);
    cudaGetSymbolAddress((void**)&w2hi, g_w2thi);
    cudaGetSymbolAddress((void**)&w2lo, g_w2tlo);

    // lazy one-time host-side infra (created on first, uncaptured call)
    static cudaStream_t s_side = nullptr;
    static cudaEvent_t ev_fork = nullptr, ev_join = nullptr;
    if (s_side == nullptr) {
        cudaStreamCreateWithFlags(&s_side, cudaStreamNonBlocking);
        cudaEventCreateWithFlags(&ev_fork, cudaEventDisableTiming);
        cudaEventCreateWithFlags(&ev_join, cudaEventDisableTiming);
    }

    const int SMEM1 = 2 * (TILE_A + TILE_Bb);            // 30720 (proj)
    const int SMEM3 = 2 * (2 * TILE_A + 2 * TILE_Bb);    // 61440 (ffn)
    cudaFuncSetAttribute(mgemm_kernel<128, 0, 1>, cudaFuncAttributeMaxDynamicSharedMemorySize, SMEM1);
    cudaFuncSetAttribute(mgemm_kernel<128, 1, 3>, cudaFuncAttributeMaxDynamicSharedMemorySize, SMEM3);
    cudaFuncSetAttribute(mgemm_kernel<512, 2, 3>, cudaFuncAttributeMaxDynamicSharedMemorySize, SMEM3);

    int mblk = (n + 127) / 128;

    // ---- fork: CSR chain on side stream ----
    cudaEventRecord(ev_fork, 0);
    cudaStreamWaitEvent(s_side, ev_fork, 0);

    zero_cnt_kernel<<<(n + 255) / 256, 256, 0, s_side>>>(n);
    hist_kernel<<<(E + 255) / 256, 256, 0, s_side>>>(dst, E);
    scan_kernel<<<1, 1024, 0, s_side>>>(n);
    scatter_kernel<<<(E + 255) / 256, 256, 0, s_side>>>(src, dst, E);
    cudaEventRecord(ev_join, s_side);

    // ---- main stream: conversions -> proj(+el/er fused, single-term) ----
    int prep_items = n * 32 + 128 * 128 + 512 * 128 + 128 * 512;
    prep_kernel<<<(prep_items + 255) / 256, 256>>>(x, fcw, w1, w2, n);

    mgemm_kernel<128, 0, 1><<<dim3(mblk, 2), 256, SMEM1>>>(
        xb, nullptr, fcwt, nullptr, a_l, a_r, nullptr, zb, nullptr, n);

    // ---- join: gat_ln needs CSR + proj ----
    cudaStreamWaitEvent(0, ev_join, 0);
    gat_ln_kernel<<<(n + 7) / 8, 256>>>(x, ln_g, ln_b, n);

    // FFN (HMMA, 3-term compensation)
    mgemm_kernel<128, 1, 3><<<dim3(mblk, 8), 256, SMEM3>>>(
        lnvhi, lnvlo, w1hi, w1lo, b1, nullptr, nullptr, inthi, intlo, n);
    mgemm_kernel<512, 2, 3><<<dim3(mblk, 2), 256, SMEM3>>>(
        inthi, intlo, w2hi, w2lo, b2, g_h_p, (float*)d_out, nullptr, nullptr, n);
}

// round 17
// speedup vs baseline: 1.3351x; 1.3230x over previous
#include <cuda_runtime.h>
#include <cuda_fp16.h>
#include <stdint.h>
#include <math.h>

#define NMAX 50000
#define EMAX 800000

// ---------------- scratch (static __device__ — no allocation) ----------------
__device__ float g_z[(size_t)NMAX * 128];        // projections fp32 (GAT gather)
__device__ float g_el[(size_t)NMAX * 8];
__device__ float g_er[(size_t)NMAX * 8];
__device__ float g_h[(size_t)NMAX * 128];        // elu(gat)+x
__device__ __half g_xh[(size_t)NMAX * 128];      // x fp16 (proj A)
__device__ __half g_lnvh[(size_t)NMAX * 128];    // layernorm(h) fp16
__device__ __half g_inth[(size_t)NMAX * 512];    // gelu(...) fp16
__device__ __half g_fcwt[128 * 128];             // B[n][k] = fc_w[h][k][o] fp16
__device__ __half g_w1t[512 * 128];              // B[n][k] = w1[k][n] fp16
__device__ __half g_w2t[128 * 512];              // B[n][k] = w2[k][n] fp16
__device__ int g_cnt[NMAX];
__device__ int g_off[NMAX + 1];
__device__ int g_cur[NMAX];
__device__ int g_csrc[EMAX];

// ---------------- helpers ----------------
__device__ __forceinline__ uint32_t smem_to_u32(const void* p) {
    uint32_t a;
    asm("{ .reg .u64 t; cvta.to.shared.u64 t, %1; cvt.u32.u64 %0, t; }" : "=r"(a) : "l"(p));
    return a;
}
__device__ __forceinline__ void ldsm_x4(uint32_t& r0, uint32_t& r1, uint32_t& r2, uint32_t& r3,
                                        uint32_t addr) {
    asm volatile("ldmatrix.sync.aligned.m8n8.x4.shared.b16 {%0,%1,%2,%3}, [%4];"
                 : "=r"(r0), "=r"(r1), "=r"(r2), "=r"(r3) : "r"(addr));
}
__device__ __forceinline__ void mma16816h(float* c, const uint32_t* a, const uint32_t* b) {
    asm volatile(
        "mma.sync.aligned.m16n8k16.row.col.f32.f16.f16.f32 "
        "{%0,%1,%2,%3}, {%4,%5,%6,%7}, {%8,%9}, {%0,%1,%2,%3};"
        : "+f"(c[0]), "+f"(c[1]), "+f"(c[2]), "+f"(c[3])
        : "r"(a[0]), "r"(a[1]), "r"(a[2]), "r"(a[3]), "r"(b[0]), "r"(b[1]));
}
__device__ __forceinline__ void cpa16(uint32_t d, const void* s) {
    asm volatile("cp.async.cg.shared.global [%0], [%1], 16;" :: "r"(d), "l"(s));
}
__device__ __forceinline__ float gelu_exact(float v) {
    return 0.5f * v * (1.0f + erff(v * 0.70710678118654752440f));
}
__device__ __forceinline__ unsigned pack_h2f(float a, float b) {
    __half2 h = __floats2half2_rn(a, b);
    return *(unsigned*)&h;
}

// =====================================================================
// fp16 HMMA GEMM, cp.async double-buffered, CTA tile 128x64,
// 3 CTAs/SM, single-sync mainloop, single-term (fp32 accum).
// EPI: 0 = proj: z -> fp32 + fused el/er (bias=a_l, res=a_r)
//      1 = ffn1: gelu(acc+bias) -> fp16
//      2 = ffn2: acc+bias+res -> fp32
// =====================================================================
#define TILE_A 10240        // A array (128 rows x 80B)
#define TILE_Bb 5120        // B array (64 rows x 80B)
#define STAGE_B (TILE_A + TILE_Bb)   // 15360

template<int KTOT, int EPI>
__global__ __launch_bounds__(256, 3) void mgemm_kernel(
    const __half* __restrict__ A, const __half* __restrict__ B,
    const float* __restrict__ bias, const float* __restrict__ res,
    float* __restrict__ outf, __half* __restrict__ outh, int M)
{
    extern __shared__ char smem[];
    const uint32_t sb = smem_to_u32(smem);

    const int tid = threadIdx.x;
    const int wid = tid >> 5, lane = tid & 31;
    const int wm = wid & 3, wn = wid >> 2;
    const int row0 = blockIdx.x * 128;
    const int col0 = blockIdx.y * 64;

    float acc[2][4][4];
#pragma unroll
    for (int i = 0; i < 2; i++)
#pragma unroll
        for (int j = 0; j < 4; j++)
#pragma unroll
            for (int p = 0; p < 4; p++) acc[i][j][p] = 0.f;

    const uint4* A4 = (const uint4*)A;
    const uint4* B4 = (const uint4*)B;
    constexpr int KU4 = KTOT / 8;
    constexpr int NK = KTOT / 32;

    const int fr0 = tid >> 2, fc0 = tid & 3;
    const int fr1 = fr0 + 64;
    const uint32_t sby0 = (uint32_t)(fr0 * 80 + fc0 * 16);
    const uint32_t sby1 = (uint32_t)(fr1 * 80 + fc0 * 16);
    int ga0 = row0 + fr0; if (ga0 > M - 1) ga0 = M - 1;
    int ga1 = row0 + fr1; if (ga1 > M - 1) ga1 = M - 1;
    const int gb0 = col0 + fr0;

    const int lg = lane >> 3, lr = lane & 7;
    const int a_row_off = lr + ((lg & 1) ? 8 : 0);
    const int a_k_off   = (lg >= 2) ? 8 : 0;
    const int b_row_off = lr + ((lg >= 2) ? 8 : 0);
    const int b_k_off   = (lg & 1) ? 8 : 0;

    auto load_stage = [&](int kc, int s) {
        const uint32_t st = sb + (uint32_t)s * STAGE_B;
        const int koff = kc * 4 + fc0;
        cpa16(st + sby0,          &A4[(size_t)ga0 * KU4 + koff]);
        cpa16(st + sby1,          &A4[(size_t)ga1 * KU4 + koff]);
        cpa16(st + TILE_A + sby0, &B4[(size_t)gb0 * KU4 + koff]);
        asm volatile("cp.async.commit_group;" ::: "memory");
    };

    load_stage(0, 0);

#pragma unroll 1
    for (int kc = 0; kc < NK; kc++) {
        asm volatile("cp.async.wait_group 0;" ::: "memory");
        __syncthreads();
        if (kc + 1 < NK) load_stage(kc + 1, (kc + 1) & 1);

        const uint32_t st = sb + (uint32_t)(kc & 1) * STAGE_B;
        const uint32_t sA_b = st, sB_b = st + TILE_A;

#pragma unroll
        for (int k16 = 0; k16 < 2; k16++) {
            const int kb = k16 * 16;
            uint32_t bfr[8];
#pragma unroll
            for (int np = 0; np < 2; np++) {
                uint32_t ab = (uint32_t)((wn * 32 + np * 16 + b_row_off) * 80 +
                                         (kb + b_k_off) * 2);
                ldsm_x4(bfr[np * 4 + 0], bfr[np * 4 + 1], bfr[np * 4 + 2], bfr[np * 4 + 3],
                        sB_b + ab);
            }
#pragma unroll
            for (int mt = 0; mt < 2; mt++) {
                uint32_t aa = (uint32_t)((wm * 32 + mt * 16 + a_row_off) * 80 +
                                         (kb + a_k_off) * 2);
                uint32_t afr[4];
                ldsm_x4(afr[0], afr[1], afr[2], afr[3], sA_b + aa);
#pragma unroll
                for (int nt = 0; nt < 4; nt++)
                    mma16816h(acc[mt][nt], afr, &bfr[nt * 2]);
            }
        }
    }

    // ---- epilogue ----
    const int gid = lane >> 2, tg = lane & 3;
    constexpr int ONST = (EPI == 1) ? 512 : 128;

    if (EPI == 0) {
        const float* alp = bias;
        const float* arp = res;
        const int cbase = col0 + wn * 32;
        float alv[2][4], arv[2][4];
#pragma unroll
        for (int hh = 0; hh < 2; hh++) {
            int hd = (cbase >> 4) + hh;
#pragma unroll
            for (int q = 0; q < 4; q++) {
                int o = (q >> 1) * 8 + tg * 2 + (q & 1);
                alv[hh][q] = alp[hd * 16 + o];
                arv[hh][q] = arp[hd * 16 + o];
            }
        }
#pragma unroll
        for (int mt = 0; mt < 2; mt++) {
#pragma unroll
            for (int half = 0; half < 2; half++) {
                int grow = row0 + wm * 32 + mt * 16 + gid + half * 8;
                bool rok = (grow < M);
#pragma unroll
                for (int nt = 0; nt < 4; nt++) {
                    int col = cbase + nt * 8 + tg * 2;
                    if (rok)
                        *(float2*)&outf[(size_t)grow * 128 + col] =
                            make_float2(acc[mt][nt][half * 2 + 0], acc[mt][nt][half * 2 + 1]);
                }
#pragma unroll
                for (int hh = 0; hh < 2; hh++) {
                    float pl = acc[mt][hh * 2 + 0][half * 2 + 0] * alv[hh][0]
                             + acc[mt][hh * 2 + 0][half * 2 + 1] * alv[hh][1]
                             + acc[mt][hh * 2 + 1][half * 2 + 0] * alv[hh][2]
                             + acc[mt][hh * 2 + 1][half * 2 + 1] * alv[hh][3];
                    float pr = acc[mt][hh * 2 + 0][half * 2 + 0] * arv[hh][0]
                             + acc[mt][hh * 2 + 0][half * 2 + 1] * arv[hh][1]
                             + acc[mt][hh * 2 + 1][half * 2 + 0] * arv[hh][2]
                             + acc[mt][hh * 2 + 1][half * 2 + 1] * arv[hh][3];
                    pl += __shfl_xor_sync(0xffffffffu, pl, 1);
                    pl += __shfl_xor_sync(0xffffffffu, pl, 2);
                    pr += __shfl_xor_sync(0xffffffffu, pr, 1);
                    pr += __shfl_xor_sync(0xffffffffu, pr, 2);
                    if (tg == 0 && rok) {
                        int hd = (cbase >> 4) + hh;
                        g_el[grow * 8 + hd] = pl;
                        g_er[grow * 8 + hd] = pr;
                    }
                }
            }
        }
    } else {
#pragma unroll
        for (int mt = 0; mt < 2; mt++) {
#pragma unroll
            for (int half = 0; half < 2; half++) {
                int grow = row0 + wm * 32 + mt * 16 + gid + half * 8;
                if (grow >= M) continue;
#pragma unroll
                for (int nt = 0; nt < 4; nt++) {
                    int col = col0 + wn * 32 + nt * 8 + tg * 2;
                    float vx = acc[mt][nt][half * 2 + 0];
                    float vy = acc[mt][nt][half * 2 + 1];
                    if (EPI == 1) {
                        vx = gelu_exact(vx + bias[col]);
                        vy = gelu_exact(vy + bias[col + 1]);
                        *(unsigned*)&outh[(size_t)grow * ONST + col] = pack_h2f(vx, vy);
                    } else {
                        const float2 rv = *(const float2*)&res[(size_t)grow * 128 + col];
                        vx += bias[col] + rv.x;
                        vy += bias[col + 1] + rv.y;
                        *(float2*)&outf[(size_t)grow * 128 + col] = make_float2(vx, vy);
                    }
                }
            }
        }
    }
}

// =====================================================================
// prep: all conversions to fp16
// =====================================================================
__global__ void prep_kernel(const float* __restrict__ x,
                            const float* __restrict__ fcw,
                            const float* __restrict__ w1,
                            const float* __restrict__ w2, int n)
{
    int id = blockIdx.x * blockDim.x + threadIdx.x;
    int nx = n * 32;
    if (id < nx) {
        float4 v = ((const float4*)x)[id];
        ((uint2*)g_xh)[id] = make_uint2(pack_h2f(v.x, v.y), pack_h2f(v.z, v.w));
        return;
    }
    id -= nx;
    if (id < 128 * 128) {
        int nn = id >> 7, k = id & 127;
        int h = nn >> 4, o = nn & 15;
        g_fcwt[id] = __float2half_rn(fcw[h * 2048 + k * 16 + o]);
        return;
    }
    id -= 128 * 128;
    if (id < 512 * 128) {
        int nn = id >> 7, k = id & 127;       // B[n][k] = w1[k][n]
        g_w1t[id] = __float2half_rn(w1[k * 512 + nn]);
        return;
    }
    id -= 512 * 128;
    if (id < 128 * 512) {
        int nn = id >> 9, k = id & 511;       // B[n][k] = w2[k][n]
        g_w2t[id] = __float2half_rn(w2[k * 128 + nn]);
    }
}

// =====================================================================
// CSR build (side-stream chain: zero -> hist -> scan -> scatter)
// =====================================================================
__global__ void zero_cnt_kernel(int n) {
    int i = blockIdx.x * blockDim.x + threadIdx.x;
    if (i < n) g_cnt[i] = 0;
}
__global__ void hist_kernel(const int* __restrict__ dst, int E) {
    int i = blockIdx.x * blockDim.x + threadIdx.x;
    if (i < E) atomicAdd(&g_cnt[dst[i]], 1);
}
__global__ __launch_bounds__(1024) void scan_kernel(int n) {
    int t = threadIdx.x;
    int chunk = (n + 1023) >> 10;
    int b = t * chunk;
    int e = b + chunk; if (e > n) e = n;
    int s = 0;
    for (int i = b; i < e; i++) s += g_cnt[i];
    int own = s;
    int lane = t & 31, w = t >> 5;
#pragma unroll
    for (int d = 1; d < 32; d <<= 1) {
        int v = __shfl_up_sync(0xffffffffu, s, d);
        if (lane >= d) s += v;
    }
    __shared__ int ws[32];
    if (lane == 31) ws[w] = s;
    __syncthreads();
    if (w == 0) {
        int v = ws[lane];
#pragma unroll
        for (int d = 1; d < 32; d <<= 1) {
            int u = __shfl_up_sync(0xffffffffu, v, d);
            if (lane >= d) v += u;
        }
        ws[lane] = v;
    }
    __syncthreads();
    int run = s - own + (w ? ws[w - 1] : 0);
    for (int i = b; i < e; i++) {
        g_off[i] = run;
        g_cur[i] = run;
        run += g_cnt[i];
    }
    if (t == 1023) g_off[n] = ws[31];
}
__global__ void scatter_kernel(const int* __restrict__ src, const int* __restrict__ dst, int E) {
    int i = blockIdx.x * blockDim.x + threadIdx.x;
    if (i < E) {
        int d = dst[i];
        int p = atomicAdd(&g_cur[d], 1);
        g_csrc[p] = src[i];
    }
}

// =====================================================================
// GAT: single-pass softmax + aggregation (fp32 z gather) + elu +
// residual + fused LN -> fp16 lnv. 4-way unrolled edge loop.
// =====================================================================
__global__ __launch_bounds__(256) void gat_ln_kernel(
    const float* __restrict__ x,
    const float* __restrict__ gg, const float* __restrict__ bb, int n)
{
    int warp = (blockIdx.x * blockDim.x + threadIdx.x) >> 5;
    int lane = threadIdx.x & 31;
    if (warp >= n) return;
    int d = warp;
    int beg = g_off[d], end = g_off[d + 1];

    int h2 = lane >> 2;
    float er_b = g_er[d * 8 + h2];

    float4 acc = make_float4(0.f, 0.f, 0.f, 0.f);
    float denom = 0.f;
    const float4* z4 = (const float4*)g_z;

    int i = beg;
    for (; i + 4 <= end; i += 4) {
        int s0 = g_csrc[i], s1 = g_csrc[i + 1], s2 = g_csrc[i + 2], s3 = g_csrc[i + 3];
        float e0 = g_el[s0 * 8 + h2] + er_b;
        float e1 = g_el[s1 * 8 + h2] + er_b;
        float e2 = g_el[s2 * 8 + h2] + er_b;
        float e3 = g_el[s3 * 8 + h2] + er_b;
        e0 = (e0 > 0.f) ? e0 : 0.01f * e0;
        e1 = (e1 > 0.f) ? e1 : 0.01f * e1;
        e2 = (e2 > 0.f) ? e2 : 0.01f * e2;
        e3 = (e3 > 0.f) ? e3 : 0.01f * e3;
        float ex0 = __expf(e0), ex1 = __expf(e1), ex2 = __expf(e2), ex3 = __expf(e3);
        float4 zv0 = z4[(size_t)s0 * 32 + lane];
        float4 zv1 = z4[(size_t)s1 * 32 + lane];
        float4 zv2 = z4[(size_t)s2 * 32 + lane];
        float4 zv3 = z4[(size_t)s3 * 32 + lane];
        denom += (ex0 + ex1) + (ex2 + ex3);
        acc.x += ex0 * zv0.x + ex1 * zv1.x + ex2 * zv2.x + ex3 * zv3.x;
        acc.y += ex0 * zv0.y + ex1 * zv1.y + ex2 * zv2.y + ex3 * zv3.y;
        acc.z += ex0 * zv0.z + ex1 * zv1.z + ex2 * zv2.z + ex3 * zv3.z;
        acc.w += ex0 * zv0.w + ex1 * zv1.w + ex2 * zv2.w + ex3 * zv3.w;
    }
    for (; i < end; i++) {
        int s0 = g_csrc[i];
        float e0 = g_el[s0 * 8 + h2] + er_b;
        e0 = (e0 > 0.f) ? e0 : 0.01f * e0;
        float ex0 = __expf(e0);
        float4 zv0 = z4[(size_t)s0 * 32 + lane];
        denom += ex0;
        acc.x += ex0 * zv0.x;
        acc.y += ex0 * zv0.y;
        acc.z += ex0 * zv0.z;
        acc.w += ex0 * zv0.w;
    }

    float rd = (denom > 0.f) ? (1.0f / denom) : 0.f;
    acc.x *= rd; acc.y *= rd; acc.z *= rd; acc.w *= rd;

    float4 xr = ((const float4*)x)[(size_t)d * 32 + lane];
    acc.x = ((acc.x > 0.f) ? acc.x : (__expf(acc.x) - 1.f)) + xr.x;
    acc.y = ((acc.y > 0.f) ? acc.y : (__expf(acc.y) - 1.f)) + xr.y;
    acc.z = ((acc.z > 0.f) ? acc.z : (__expf(acc.z) - 1.f)) + xr.z;
    acc.w = ((acc.w > 0.f) ? acc.w : (__expf(acc.w) - 1.f)) + xr.w;
    ((float4*)g_h)[(size_t)d * 32 + lane] = acc;

    float s = acc.x + acc.y + acc.z + acc.w;
#pragma unroll
    for (int o = 16; o; o >>= 1) s += __shfl_xor_sync(0xffffffffu, s, o);
    float mu = s * (1.f / 128.f);
    float dx = acc.x - mu, dy = acc.y - mu, dz = acc.z - mu, dw = acc.w - mu;
    float q = dx * dx + dy * dy + dz * dz + dw * dw;
#pragma unroll
    for (int o = 16; o; o >>= 1) q += __shfl_xor_sync(0xffffffffu, q, o);
    float rs = rsqrtf(q * (1.f / 128.f) + 1e-6f);
    float4 g4 = ((const float4*)gg)[lane];
    float4 b4 = ((const float4*)bb)[lane];
    float4 o4 = make_float4(dx * rs * g4.x + b4.x, dy * rs * g4.y + b4.y,
                            dz * rs * g4.z + b4.z, dw * rs * g4.w + b4.w);
    ((uint2*)g_lnvh)[(size_t)d * 32 + lane] =
        make_uint2(pack_h2f(o4.x, o4.y), pack_h2f(o4.z, o4.w));
}

// =====================================================================
extern "C" void kernel_launch(void* const* d_in, const int* in_sizes, int n_in,
                              void* d_out, int out_size)
{
    const float* x    = (const float*)d_in[0];
    const float* fcw  = (const float*)d_in[1];
    const float* a_l  = (const float*)d_in[2];
    const float* a_r  = (const float*)d_in[3];
    const float* ln_g = (const float*)d_in[4];
    const float* ln_b = (const float*)d_in[5];
    const float* w1   = (const float*)d_in[6];
    const float* b1   = (const float*)d_in[7];
    const float* w2   = (const float*)d_in[8];
    const float* b2   = (const float*)d_in[9];
    const int*   src  = (const int*)d_in[10];
    const int*   dst  = (const int*)d_in[11];

    int n = in_sizes[0] / 128;
    int E = in_sizes[10];

    float *g_z_p, *g_h_p;
    __half *xh, *lnvh, *inth, *fcwt, *w1t, *w2t;
    cudaGetSymbolAddress((void**)&g_z_p, g_z);
    cudaGetSymbolAddress((void**)&g_h_p, g_h);
    cudaGetSymbolAddress((void**)&xh, g_xh);
    cudaGetSymbolAddress((void**)&lnvh, g_lnvh);
    cudaGetSymbolAddress((void**)&inth, g_inth);
    cudaGetSymbolAddress((void**)&fcwt, g_fcwt);
    cudaGetSymbolAddress((void**)&w1t, g_w1t);
    cudaGetSymbolAddress((void**)&w2t, g_w2t);

    // lazy one-time host-side infra (created on first, uncaptured call)
    static cudaStream_t s_side = nullptr;
    static cudaEvent_t ev_fork = nullptr, ev_join = nullptr;
    if (s_side == nullptr) {
        cudaStreamCreateWithFlags(&s_side, cudaStreamNonBlocking);
        cudaEventCreateWithFlags(&ev_fork, cudaEventDisableTiming);
        cudaEventCreateWithFlags(&ev_join, cudaEventDisableTiming);
    }

    const int SMEM_SZ = 2 * STAGE_B;   // 30720
    cudaFuncSetAttribute(mgemm_kernel<128, 0>, cudaFuncAttributeMaxDynamicSharedMemorySize, SMEM_SZ);
    cudaFuncSetAttribute(mgemm_kernel<128, 1>, cudaFuncAttributeMaxDynamicSharedMemorySize, SMEM_SZ);
    cudaFuncSetAttribute(mgemm_kernel<512, 2>, cudaFuncAttributeMaxDynamicSharedMemorySize, SMEM_SZ);

    int mblk = (n + 127) / 128;

    // ---- fork: CSR chain on side stream ----
    cudaEventRecord(ev_fork, 0);
    cudaStreamWaitEvent(s_side, ev_fork, 0);

    zero_cnt_kernel<<<(n + 255) / 256, 256, 0, s_side>>>(n);
    hist_kernel<<<(E + 255) / 256, 256, 0, s_side>>>(dst, E);
    scan_kernel<<<1, 1024, 0, s_side>>>(n);
    scatter_kernel<<<(E + 255) / 256, 256, 0, s_side>>>(src, dst, E);
    cudaEventRecord(ev_join, s_side);

    // ---- main stream: conversions -> proj (fp16, fused el/er) ----
    int prep_items = n * 32 + 128 * 128 + 512 * 128 + 128 * 512;
    prep_kernel<<<(prep_items + 255) / 256, 256>>>(x, fcw, w1, w2, n);

    mgemm_kernel<128, 0><<<dim3(mblk, 2), 256, SMEM_SZ>>>(
        xh, fcwt, a_l, a_r, g_z_p, nullptr, n);

    // ---- join: gat_ln needs CSR + proj ----
    cudaStreamWaitEvent(0, ev_join, 0);
    gat_ln_kernel<<<(n + 7) / 8, 256>>>(x, ln_g, ln_b, n);

    // FFN (fp16 HMMA)
    mgemm_kernel<128, 1><<<dim3(mblk, 8), 256, SMEM_SZ>>>(
        lnvh, w1t, b1, nullptr, nullptr, inth, n);
    mgemm_kernel<512, 2><<<dim3(mblk, 2), 256, SMEM_SZ>>>(
        inth, w2t, b2, g_h_p, (float*)d_out, nullptr, n);
}